// round 1
// baseline (speedup 1.0000x reference)
#include <cuda_runtime.h>

#define NN 50000
#define NE 800000
#define DIM 128
#define NO 384   /* 3*HIDDEN */

// ---------------- scratch (device globals: allocation-free) ----------------
__device__ float g_aggf[(size_t)NN * DIM];   // segment-sum of norm_src*feat
__device__ float g_aggh[(size_t)NN * DIM];   // segment-sum of norm_src*hx
__device__ float g_C1[(size_t)NN * NO];      // (aggf*ndst) @ W_i
__device__ float g_C2[(size_t)NN * NO];      // (aggh*ndst) @ W_h
__device__ float g_WiT[NO * DIM];            // W_i transposed [n][k]
__device__ float g_WhT[NO * DIM];
__device__ float g_nsrc[NN];
__device__ float g_ndst[NN];
__device__ int   g_degout[NN];
__device__ int   g_degin[NN];

// ---------------- kernel 1: zero accumulators + degrees ----------------
__global__ void zero_kernel() {
    int tid = blockIdx.x * blockDim.x + threadIdx.x;
    int nt = gridDim.x * blockDim.x;
    const int total4 = NN * DIM / 4;
    float4 z = make_float4(0.f, 0.f, 0.f, 0.f);
    for (int p = tid; p < total4; p += nt) {
        reinterpret_cast<float4*>(g_aggf)[p] = z;
        reinterpret_cast<float4*>(g_aggh)[p] = z;
    }
    for (int p = tid; p < NN; p += nt) { g_degout[p] = 0; g_degin[p] = 0; }
}

// ---------------- kernel 2: degrees ----------------
__global__ void deg_kernel(const int* __restrict__ src, const int* __restrict__ dst) {
    int e = blockIdx.x * blockDim.x + threadIdx.x;
    if (e < NE) {
        atomicAdd(&g_degout[src[e]], 1);
        atomicAdd(&g_degin[dst[e]], 1);
    }
}

// ---------------- kernel 3: norms + W transpose ----------------
__global__ void prep_kernel(const float* __restrict__ Wi, const float* __restrict__ Wh) {
    int i = blockIdx.x * blockDim.x + threadIdx.x;
    if (i < NN) {
        g_nsrc[i] = rsqrtf(fmaxf((float)g_degout[i], 1.f));
        g_ndst[i] = rsqrtf(fmaxf((float)g_degin[i], 1.f));
    }
    if (i < DIM * NO) {
        int k = i / NO, n = i % NO;
        g_WiT[n * DIM + k] = Wi[i];
        g_WhT[n * DIM + k] = Wh[i];
    }
}

// ---------------- kernel 4: edge gather + reduce-scatter (warp per edge) ----------------
__global__ __launch_bounds__(256) void scatter_kernel(
    const float* __restrict__ feat, const float* __restrict__ hx,
    const int* __restrict__ src, const int* __restrict__ dst)
{
    int gtid = blockIdx.x * blockDim.x + threadIdx.x;
    int e = gtid >> 5;
    int lane = gtid & 31;
    if (e >= NE) return;
    int s = __ldg(src + e);
    int d = __ldg(dst + e);
    float ns = g_nsrc[s];
    float4 f = reinterpret_cast<const float4*>(feat + (size_t)s * DIM)[lane];
    float4 h = reinterpret_cast<const float4*>(hx + (size_t)s * DIM)[lane];
    f.x *= ns; f.y *= ns; f.z *= ns; f.w *= ns;
    h.x *= ns; h.y *= ns; h.z *= ns; h.w *= ns;
    unsigned long long pf = (unsigned long long)__cvta_generic_to_global(g_aggf + (size_t)d * DIM + lane * 4);
    unsigned long long ph = (unsigned long long)__cvta_generic_to_global(g_aggh + (size_t)d * DIM + lane * 4);
    asm volatile("red.global.add.v4.f32 [%0], {%1,%2,%3,%4};"
                 :: "l"(pf), "f"(f.x), "f"(f.y), "f"(f.z), "f"(f.w) : "memory");
    asm volatile("red.global.add.v4.f32 [%0], {%1,%2,%3,%4};"
                 :: "l"(ph), "f"(h.x), "f"(h.y), "f"(h.z), "f"(h.w) : "memory");
}

// ---------------- kernel 5: fp32 GEMM  C = (agg * ndst) @ W  ----------------
// 64x64 tile, K=128 single pass. A and B both k-major in smem (float4 granularity)
// with an XOR swizzle that includes row bit 5 so column-of-rows LDS.128 reads are
// conflict-free (2 phases, no bank conflicts).
#define SWZ(r, k4) ((k4) ^ ((r) & 31) ^ (((r) & 32) >> 1))

__global__ __launch_bounds__(256) void gemm_kernel() {
    extern __shared__ float4 sm[];
    float4* As = sm;             // [64][32]
    float4* Bs = sm + 64 * 32;   // [64][32]
    int t = threadIdx.x;
    int m0 = blockIdx.x * 64;
    int n0 = blockIdx.y * 64;
    const float* A  = blockIdx.z ? g_aggh : g_aggf;
    const float* WT = blockIdx.z ? g_WhT : g_WiT;
    float* C        = blockIdx.z ? g_C2  : g_C1;

#pragma unroll
    for (int i = 0; i < 8; i++) {
        int p = t + i * 256;
        int r = p >> 5, k4 = p & 31;
        int gm = m0 + r;
        float4 v = make_float4(0.f, 0.f, 0.f, 0.f);
        if (gm < NN) {
            float nd = g_ndst[gm];
            v = reinterpret_cast<const float4*>(A + (size_t)gm * DIM)[k4];
            v.x *= nd; v.y *= nd; v.z *= nd; v.w *= nd;
        }
        As[r * 32 + SWZ(r, k4)] = v;
        Bs[r * 32 + SWZ(r, k4)] =
            reinterpret_cast<const float4*>(WT + (size_t)(n0 + r) * DIM)[k4];
    }
    __syncthreads();

    int tm = (t & 15) * 4;   // 4 consecutive M rows
    int tn = (t >> 4) * 4;   // 4 consecutive N cols
    float acc[4][4] = {};
#pragma unroll 4
    for (int k4 = 0; k4 < 32; k4++) {
        float4 a[4], b[4];
#pragma unroll
        for (int i = 0; i < 4; i++) a[i] = As[(tm + i) * 32 + SWZ(tm + i, k4)];
#pragma unroll
        for (int j = 0; j < 4; j++) b[j] = Bs[(tn + j) * 32 + SWZ(tn + j, k4)];
#pragma unroll
        for (int i = 0; i < 4; i++)
#pragma unroll
            for (int j = 0; j < 4; j++)
                acc[i][j] += a[i].x * b[j].x + a[i].y * b[j].y +
                             a[i].z * b[j].z + a[i].w * b[j].w;
    }

#pragma unroll
    for (int i = 0; i < 4; i++) {
        int gm = m0 + tm + i;
        if (gm < NN) {
            float4 o = make_float4(acc[i][0], acc[i][1], acc[i][2], acc[i][3]);
            *reinterpret_cast<float4*>(C + (size_t)gm * NO + n0 + tn) = o;
        }
    }
}

// ---------------- kernel 6: GRU gating ----------------
__global__ __launch_bounds__(256) void gru_kernel(
    const float* __restrict__ hx, const float* __restrict__ bi,
    const float* __restrict__ bh, float* __restrict__ out)
{
    int idx = blockIdx.x * blockDim.x + threadIdx.x;
    if (idx >= NN * DIM) return;
    int n = idx >> 7, c = idx & 127;
    const float* c1 = g_C1 + (size_t)n * NO;
    const float* c2 = g_C2 + (size_t)n * NO;
    float rsum = c1[c]       + c2[c]       + bi[c]       + bh[c];
    float zsum = c1[c + 128] + c2[c + 128] + bi[c + 128] + bh[c + 128];
    float in_  = c1[c + 256] + bi[c + 256];
    float hn   = c2[c + 256] + bh[c + 256];
    float r = 1.f / (1.f + __expf(-rsum));
    float z = 1.f / (1.f + __expf(-zsum));
    float nn = tanhf(in_ + r * hn);
    out[idx] = (1.f - z) * nn + z * hx[idx];
}

// ---------------- launch ----------------
extern "C" void kernel_launch(void* const* d_in, const int* in_sizes, int n_in,
                              void* d_out, int out_size)
{
    const float* feat = (const float*)d_in[0];
    const float* hx   = (const float*)d_in[1];
    const float* Wi   = (const float*)d_in[2];
    const float* bi   = (const float*)d_in[3];
    const float* Wh   = (const float*)d_in[4];
    const float* bh   = (const float*)d_in[5];
    const int*   src  = (const int*)d_in[6];
    const int*   dst  = (const int*)d_in[7];
    float* out = (float*)d_out;

    cudaFuncSetAttribute(gemm_kernel, cudaFuncAttributeMaxDynamicSharedMemorySize, 65536);

    zero_kernel<<<512, 256>>>();
    deg_kernel<<<(NE + 255) / 256, 256>>>(src, dst);
    prep_kernel<<<(NN + 255) / 256, 256>>>(Wi, Wh);
    scatter_kernel<<<(NE * 32) / 256, 256>>>(feat, hx, src, dst);
    gemm_kernel<<<dim3((NN + 63) / 64, NO / 64, 2), 256, 65536>>>();
    gru_kernel<<<(NN * DIM + 255) / 256, 256>>>(hx, bi, bh, out);
}

// round 3
// speedup vs baseline: 2.4971x; 2.4971x over previous
#include <cuda_runtime.h>
#include <cuda_bf16.h>
#include <cstdint>

#define NN 50000
#define NE 800000
#define DIM 128
#define NO 384   /* 3*HIDDEN */

// ---------------- scratch (device globals: allocation-free) ----------------
__device__ float g_aggf[(size_t)NN * DIM];
__device__ float g_aggh[(size_t)NN * DIM];
__device__ float g_C1[(size_t)NN * NO];
__device__ float g_C2[(size_t)NN * NO];
__device__ __nv_bfloat16 g_Afh[(size_t)NN * DIM];  // hi(ndst * aggf)
__device__ __nv_bfloat16 g_Afl[(size_t)NN * DIM];  // lo
__device__ __nv_bfloat16 g_Ahh[(size_t)NN * DIM];
__device__ __nv_bfloat16 g_Ahl[(size_t)NN * DIM];
__device__ __nv_bfloat16 g_Bih[NO * DIM];          // Wi^T hi  [n][k]
__device__ __nv_bfloat16 g_Bil[NO * DIM];
__device__ __nv_bfloat16 g_Bhh[NO * DIM];
__device__ __nv_bfloat16 g_Bhl[NO * DIM];
__device__ float g_nsrc[NN];
__device__ float g_ndst[NN];
__device__ int   g_degout[NN];
__device__ int   g_degin[NN];

__device__ __forceinline__ uint32_t smem_u32(const void* p) {
    uint32_t a;
    asm("{ .reg .u64 t; cvta.to.shared.u64 t, %1; cvt.u32.u64 %0, t; }" : "=r"(a) : "l"(p));
    return a;
}

// ---------------- kernel 1: zero accumulators + degrees ----------------
__global__ void zero_kernel() {
    int tid = blockIdx.x * blockDim.x + threadIdx.x;
    int nt = gridDim.x * blockDim.x;
    const int total4 = NN * DIM / 4;
    float4 z = make_float4(0.f, 0.f, 0.f, 0.f);
    for (int p = tid; p < total4; p += nt) {
        reinterpret_cast<float4*>(g_aggf)[p] = z;
        reinterpret_cast<float4*>(g_aggh)[p] = z;
    }
    for (int p = tid; p < NN; p += nt) { g_degout[p] = 0; g_degin[p] = 0; }
}

// ---------------- kernel 2: degrees ----------------
__global__ void deg_kernel(const int* __restrict__ src, const int* __restrict__ dst) {
    int e = blockIdx.x * blockDim.x + threadIdx.x;
    if (e < NE) {
        atomicAdd(&g_degout[src[e]], 1);
        atomicAdd(&g_degin[dst[e]], 1);
    }
}

// ---------------- kernel 3: norms ----------------
__global__ void prep_kernel() {
    int i = blockIdx.x * blockDim.x + threadIdx.x;
    if (i < NN) {
        g_nsrc[i] = rsqrtf(fmaxf((float)g_degout[i], 1.f));
        g_ndst[i] = rsqrtf(fmaxf((float)g_degin[i], 1.f));
    }
}

// ---------------- kernel 4: edge gather + reduce-scatter (warp per edge) ----------------
__global__ __launch_bounds__(256) void scatter_kernel(
    const float* __restrict__ feat, const float* __restrict__ hx,
    const int* __restrict__ src, const int* __restrict__ dst)
{
    int gtid = blockIdx.x * blockDim.x + threadIdx.x;
    int e = gtid >> 5;
    int lane = gtid & 31;
    if (e >= NE) return;
    int s = __ldg(src + e);
    int d = __ldg(dst + e);
    float ns = g_nsrc[s];
    float4 f = reinterpret_cast<const float4*>(feat + (size_t)s * DIM)[lane];
    float4 h = reinterpret_cast<const float4*>(hx + (size_t)s * DIM)[lane];
    f.x *= ns; f.y *= ns; f.z *= ns; f.w *= ns;
    h.x *= ns; h.y *= ns; h.z *= ns; h.w *= ns;
    unsigned long long pf = (unsigned long long)__cvta_generic_to_global(g_aggf + (size_t)d * DIM + lane * 4);
    unsigned long long ph = (unsigned long long)__cvta_generic_to_global(g_aggh + (size_t)d * DIM + lane * 4);
    asm volatile("red.global.add.v4.f32 [%0], {%1,%2,%3,%4};"
                 :: "l"(pf), "f"(f.x), "f"(f.y), "f"(f.z), "f"(f.w) : "memory");
    asm volatile("red.global.add.v4.f32 [%0], {%1,%2,%3,%4};"
                 :: "l"(ph), "f"(h.x), "f"(h.y), "f"(h.z), "f"(h.w) : "memory");
}

// ---------------- kernel 5: fp32 -> bf16 hi/lo split ----------------
__global__ __launch_bounds__(256) void convert_kernel(
    const float* __restrict__ Wi, const float* __restrict__ Wh)
{
    int idx = blockIdx.x * blockDim.x + threadIdx.x;
    if (idx < NN * DIM) {
        int n = idx >> 7;
        float nd = g_ndst[n];
        float af = g_aggf[idx] * nd;
        float ah = g_aggh[idx] * nd;
        __nv_bfloat16 afh = __float2bfloat16(af);
        __nv_bfloat16 ahh = __float2bfloat16(ah);
        g_Afh[idx] = afh;
        g_Afl[idx] = __float2bfloat16(af - __bfloat162float(afh));
        g_Ahh[idx] = ahh;
        g_Ahl[idx] = __float2bfloat16(ah - __bfloat162float(ahh));
    }
    if (idx < NO * DIM) {
        int n = idx >> 7, k = idx & 127;
        float wi = Wi[k * NO + n];
        float wh = Wh[k * NO + n];
        __nv_bfloat16 wih = __float2bfloat16(wi);
        __nv_bfloat16 whh = __float2bfloat16(wh);
        g_Bih[idx] = wih;
        g_Bil[idx] = __float2bfloat16(wi - __bfloat162float(wih));
        g_Bhh[idx] = whh;
        g_Bhl[idx] = __float2bfloat16(wh - __bfloat162float(whh));
    }
}

// ---------------- kernel 6: mma.sync bf16 split GEMM ----------------
// CTA tile 128(M) x 128(N), K = 3 passes x 128. 8 warps as 2(M) x 4(N),
// each warp 64x32 via m16n8k16 HMMA. Smem pitch padded to 272B: conflict-free
// ldmatrix. D = Ah@Bh + Al@Bh + Ah@Bl, fp32 accumulators.
#define PITCH 136                      /* bf16 elements per smem row (272B) */
#define SB_OFF (128 * PITCH * 2)       /* byte offset of B region */
#define GEMM_SMEM (2 * 128 * PITCH * 2)

__global__ __launch_bounds__(256) void gemm_kernel() {
    extern __shared__ char smem[];
    uint32_t sAa = smem_u32(smem);
    uint32_t sBa = sAa + SB_OFF;
    int tid = threadIdx.x, lane = tid & 31, wid = tid >> 5;
    int warp_m = wid & 1, warp_n = wid >> 1;
    int m0 = blockIdx.x * 128, n0 = blockIdx.y * 128;
    const __nv_bfloat16* Ahi = blockIdx.z ? g_Ahh : g_Afh;
    const __nv_bfloat16* Alo = blockIdx.z ? g_Ahl : g_Afl;
    const __nv_bfloat16* Bhi = blockIdx.z ? g_Bhh : g_Bih;
    const __nv_bfloat16* Blo = blockIdx.z ? g_Bhl : g_Bil;
    float* C                 = blockIdx.z ? g_C2  : g_C1;

    float acc[4][4][4];
#pragma unroll
    for (int mi = 0; mi < 4; mi++)
#pragma unroll
        for (int ni = 0; ni < 4; ni++)
#pragma unroll
            for (int j = 0; j < 4; j++) acc[mi][ni][j] = 0.f;

    // ldmatrix lane->row/col mapping
    int a_row = (lane & 7) + ((lane >> 3) & 1) * 8;   // m within 16
    int a_kof = (lane >> 4) * 8;                      // k offset 0/8
    int b_row = (lane & 7) + (lane >> 4) * 8;         // n within 16
    int b_kof = ((lane >> 3) & 1) * 8;                // k offset 0/8

#pragma unroll 1
    for (int pass = 0; pass < 3; pass++) {
        const uint4* Asrc = reinterpret_cast<const uint4*>((pass == 1) ? Alo : Ahi);
        const uint4* Bsrc = reinterpret_cast<const uint4*>((pass == 2) ? Blo : Bhi);
        __syncthreads();
#pragma unroll
        for (int i = 0; i < 8; i++) {
            int p = tid + i * 256;            // 2048 uint4 per tile
            int r = p >> 4, q = p & 15;
            int gm = m0 + r;
            uint4 va = make_uint4(0u, 0u, 0u, 0u);
            if (gm < NN) va = Asrc[gm * 16 + q];
            *reinterpret_cast<uint4*>(smem + (r * PITCH + q * 8) * 2) = va;
            uint4 vb = Bsrc[(n0 + r) * 16 + q];
            *reinterpret_cast<uint4*>(smem + SB_OFF + (r * PITCH + q * 8) * 2) = vb;
        }
        __syncthreads();

#pragma unroll
        for (int ks = 0; ks < 8; ks++) {
            int k0 = ks * 16;
            uint32_t a[4][4], b[4][2];
#pragma unroll
            for (int mi = 0; mi < 4; mi++) {
                uint32_t addr = sAa + ((warp_m * 64 + mi * 16 + a_row) * PITCH + k0 + a_kof) * 2;
                asm volatile("ldmatrix.sync.aligned.m8n8.x4.shared.b16 {%0,%1,%2,%3}, [%4];"
                             : "=r"(a[mi][0]), "=r"(a[mi][1]), "=r"(a[mi][2]), "=r"(a[mi][3])
                             : "r"(addr));
            }
#pragma unroll
            for (int nh = 0; nh < 2; nh++) {
                uint32_t addr = sBa + ((warp_n * 32 + nh * 16 + b_row) * PITCH + k0 + b_kof) * 2;
                uint32_t r0, r1, r2, r3;
                asm volatile("ldmatrix.sync.aligned.m8n8.x4.shared.b16 {%0,%1,%2,%3}, [%4];"
                             : "=r"(r0), "=r"(r1), "=r"(r2), "=r"(r3)
                             : "r"(addr));
                b[nh * 2][0] = r0; b[nh * 2][1] = r1;
                b[nh * 2 + 1][0] = r2; b[nh * 2 + 1][1] = r3;
            }
#pragma unroll
            for (int mi = 0; mi < 4; mi++)
#pragma unroll
                for (int ni = 0; ni < 4; ni++) {
                    asm volatile(
                        "mma.sync.aligned.m16n8k16.row.col.f32.bf16.bf16.f32 "
                        "{%0,%1,%2,%3}, {%4,%5,%6,%7}, {%8,%9}, {%0,%1,%2,%3};"
                        : "+f"(acc[mi][ni][0]), "+f"(acc[mi][ni][1]),
                          "+f"(acc[mi][ni][2]), "+f"(acc[mi][ni][3])
                        : "r"(a[mi][0]), "r"(a[mi][1]), "r"(a[mi][2]), "r"(a[mi][3]),
                          "r"(b[ni][0]), "r"(b[ni][1]));
                }
        }
    }

    // ---- epilogue ----
#pragma unroll
    for (int mi = 0; mi < 4; mi++) {
        int row = m0 + warp_m * 64 + mi * 16 + (lane >> 2);
#pragma unroll
        for (int ni = 0; ni < 4; ni++) {
            int col = n0 + warp_n * 32 + ni * 8 + (lane & 3) * 2;
            if (row < NN) {
                float2 v0 = make_float2(acc[mi][ni][0], acc[mi][ni][1]);
                *reinterpret_cast<float2*>(C + (size_t)row * NO + col) = v0;
            }
            if (row + 8 < NN) {
                float2 v1 = make_float2(acc[mi][ni][2], acc[mi][ni][3]);
                *reinterpret_cast<float2*>(C + (size_t)(row + 8) * NO + col) = v1;
            }
        }
    }
}

// ---------------- kernel 7: GRU gating ----------------
__global__ __launch_bounds__(256) void gru_kernel(
    const float* __restrict__ hx, const float* __restrict__ bi,
    const float* __restrict__ bh, float* __restrict__ out)
{
    int idx = blockIdx.x * blockDim.x + threadIdx.x;
    if (idx >= NN * DIM) return;
    int n = idx >> 7, c = idx & 127;
    const float* c1 = g_C1 + (size_t)n * NO;
    const float* c2 = g_C2 + (size_t)n * NO;
    float rsum = c1[c]       + c2[c]       + bi[c]       + bh[c];
    float zsum = c1[c + 128] + c2[c + 128] + bi[c + 128] + bh[c + 128];
    float in_  = c1[c + 256] + bi[c + 256];
    float hn   = c2[c + 256] + bh[c + 256];
    float r = 1.f / (1.f + __expf(-rsum));
    float z = 1.f / (1.f + __expf(-zsum));
    float nn = tanhf(in_ + r * hn);
    out[idx] = (1.f - z) * nn + z * hx[idx];
}

// ---------------- launch ----------------
extern "C" void kernel_launch(void* const* d_in, const int* in_sizes, int n_in,
                              void* d_out, int out_size)
{
    const float* feat = (const float*)d_in[0];
    const float* hx   = (const float*)d_in[1];
    const float* Wi   = (const float*)d_in[2];
    const float* bi   = (const float*)d_in[3];
    const float* Wh   = (const float*)d_in[4];
    const float* bh   = (const float*)d_in[5];
    const int*   src  = (const int*)d_in[6];
    const int*   dst  = (const int*)d_in[7];
    float* out = (float*)d_out;

    cudaFuncSetAttribute(gemm_kernel, cudaFuncAttributeMaxDynamicSharedMemorySize, GEMM_SMEM);

    zero_kernel<<<512, 256>>>();
    deg_kernel<<<(NE + 255) / 256, 256>>>(src, dst);
    prep_kernel<<<(NN + 255) / 256, 256>>>();
    scatter_kernel<<<(NE * 32) / 256, 256>>>(feat, hx, src, dst);
    convert_kernel<<<(NN * DIM + 255) / 256, 256>>>(Wi, Wh);
    gemm_kernel<<<dim3((NN + 127) / 128, NO / 128, 2), 256, GEMM_SMEM>>>();
    gru_kernel<<<(NN * DIM + 255) / 256, 256>>>(hx, bi, bh, out);
}